// round 12
// baseline (speedup 1.0000x reference)
#include <cuda_runtime.h>
#include <cuda_fp16.h>
#include <cstdint>
#include <cstddef>

#define SLEN  2048
#define BATCH 32
#define DDIM  1024
#define E2V   1024
#define MROWS (SLEN*BATCH)

// score GEMM tiling: block 256x128, 8 warps (4x2), warp tile 64x64, BK=64
#define BM 256
#define BN 128
#define BK 64
#define NKI (E2V/BK)     // 16 k-iterations
#define NCB (DDIM/BN)    // 8 column blocks
#define NRB (MROWS/BM)   // 256 row blocks

// dynamic smem: 2-stage A (32KB) + 2-stage B (16KB) + Wa  => 2 CTAs/SM
#define OFF_A   0u
#define OFF_B   65536u
#define OFF_WA  98304u
#define SMEM_TOTAL 98816u

// fused prepass grid ranges
#define PB_APACK  8192           // 256 rowblks x 32 kb
#define PB_WCPACK 1024
#define PB_WS     1024
#define PB_ZERO   256
#define PB_TOTAL  (PB_APACK+PB_WCPACK+PB_WS+PB_ZERO)

// Device-global scratch (no runtime allocation allowed).
__device__ float g_ws[BATCH*DDIM];     // ws[b][d]
__device__ float g_score[MROWS];       // r = s*32+b
__device__ float g_attn[MROWS];
// enc pre-converted fp16, mma-A-fragment packed: per (rowblk,kb32) 16KB tile
__device__ __align__(16) __half g_apack[(size_t)MROWS*E2V];   // 128 MB
// Wc pre-converted fp16, mma-B-fragment packed: per (cb,kb32) 8KB tile
__device__ __align__(16) __half g_wcb[(size_t)DDIM*E2V];      // 2 MB

// ---------------------------------------------------------------- helpers
__device__ __forceinline__ uint32_t smem_u32(const void* p){
    uint32_t a;
    asm("{ .reg .u64 t; cvta.to.shared.u64 t, %1; cvt.u32.u64 %0, t; }"
        : "=r"(a) : "l"(p));
    return a;
}
__device__ __forceinline__ float fast_tanh(float x){
    float r; asm("tanh.approx.f32 %0, %1;" : "=f"(r) : "f"(x)); return r;
}
__device__ __forceinline__ void cp16(uint32_t dst, const void* src){
    asm volatile("cp.async.cg.shared.global [%0], [%1], 16;" :: "r"(dst), "l"(src));
}
__device__ __forceinline__ void lds128(uint32_t* r, uint32_t addr){
    asm volatile("ld.shared.v4.b32 {%0,%1,%2,%3}, [%4];"
                 : "=r"(r[0]), "=r"(r[1]), "=r"(r[2]), "=r"(r[3]) : "r"(addr));
}
__device__ __forceinline__ void mma_f16(float* c, const uint32_t* a,
                                        uint32_t b0, uint32_t b1){
    asm volatile(
      "mma.sync.aligned.m16n8k16.row.col.f32.f16.f16.f32 "
      "{%0,%1,%2,%3}, {%4,%5,%6,%7}, {%8,%9}, {%0,%1,%2,%3};\n"
      : "+f"(c[0]), "+f"(c[1]), "+f"(c[2]), "+f"(c[3])
      : "r"(a[0]), "r"(a[1]), "r"(a[2]), "r"(a[3]), "r"(b0), "r"(b1));
}

// ---------------------------------------------------------------- prepass bodies
// enc [rows][1024] fp32 -> fp16 A-fragment packed 16KB tiles (per rowblk,kb32).
__device__ void apack_body(const float* __restrict__ enc, int R, int kb,
                           __half2 (*s2)[17], int tid){
    const float* src = enc + (size_t)R*256*E2V + kb*32;
    #pragma unroll
    for (int j=0;j<8;j++){
        int idx = tid + j*256;               // 0..2047 float4s
        int row = idx >> 3, kq = (idx & 7) << 2;
        float4 v = *reinterpret_cast<const float4*>(src + (size_t)row*E2V + kq);
        s2[row][(kq>>1)  ] = __floats2half2_rn(v.x, v.y);
        s2[row][(kq>>1)+1] = __floats2half2_rn(v.z, v.w);
    }
    __syncthreads();
    uint4* outp = (uint4*)((char*)g_apack + (size_t)(R*32 + kb)*16384);
    #pragma unroll
    for (int j=0;j<4;j++){
        int f = tid + j*256;                 // 0..1023 fragments
        int lane = f & 31, ks = (f>>5)&1, mgrp = f>>6;
        int g = lane >> 2, t = lane & 3;
        int r0 = mgrp*16 + g, c = ks*8 + t;
        uint32_t q0 = *(const uint32_t*)&s2[r0  ][c  ];
        uint32_t q1 = *(const uint32_t*)&s2[r0+8][c  ];
        uint32_t q2 = *(const uint32_t*)&s2[r0  ][c+4];
        uint32_t q3 = *(const uint32_t*)&s2[r0+8][c+4];
        outp[f] = make_uint4(q0,q1,q2,q3);
    }
}

// Wc [1024 n][1024 k] fp32 -> fp16 B-fragment packed 8KB tiles (per cb,kb32).
__device__ void wcpack_body(const float* __restrict__ Wc, int blk, int tid){
    int id = blk*256 + tid;                  // 0..262143
    int n  = id >> 8;
    int k4 = (id & 255) << 2;
    float4 v = *reinterpret_cast<const float4*>(Wc + (size_t)n*E2V + k4);
    __half2 p01 = __floats2half2_rn(v.x, v.y);
    __half2 p23 = __floats2half2_rn(v.z, v.w);
    int cb = n >> 7, n7 = n & 127;
    int ngrp2 = n7 >> 4, s8 = (n7>>3)&1, g = n7 & 7;
    int kb = k4 >> 5, kk = k4 & 31;
    int ks = kk >> 4, kk16 = kk & 15;
    int t  = (kk16 & 7) >> 1, bh = kk16 >> 3;
    size_t base = (size_t)(cb*32 + kb)*8192
                + (size_t)(((ngrp2*2+ks)*32 + g*4 + t)*16 + s8*8 + bh*4);
    *(uint32_t*)((char*)g_wcb + base     ) = *(uint32_t*)&p01;
    *(uint32_t*)((char*)g_wcb + base + 16) = *(uint32_t*)&p23;
}

// ws[b][e] = sum_d h[b,d] * Wb[e,d]
__device__ void ws_body(const float* __restrict__ h, const float* __restrict__ Wb,
                        int e, int tid){
    int w    = tid >> 5;
    int lane = tid & 31;
    float wreg[32];
    #pragma unroll
    for (int i=0;i<32;i++) wreg[i] = Wb[(size_t)e*DDIM + i*32 + lane];
    for (int j=0;j<4;j++){
        int b = j*8 + w;
        const float* hr = h + (size_t)b*DDIM;
        float acc = 0.f;
        #pragma unroll
        for (int i=0;i<32;i++) acc = fmaf(wreg[i], hr[i*32+lane], acc);
        #pragma unroll
        for (int o=16;o>0;o>>=1) acc += __shfl_xor_sync(0xffffffffu, acc, o);
        if (lane==0) g_ws[(size_t)b*DDIM + e] = acc;
    }
}

__device__ void zero_body(float* __restrict__ out, int blk, int tid){
    int i = blk*256 + tid;
    if (i < MROWS)     g_score[i] = 0.f;
    if (i < BATCH*E2V) out[i]     = 0.f;
}

// One launch; block ranges dispatch to independent prepass jobs.
__global__ __launch_bounds__(256) void prepass_kernel(
        const float* __restrict__ enc, const float* __restrict__ Wc,
        const float* __restrict__ h,   const float* __restrict__ Wb,
        float* __restrict__ out){
    __shared__ __half2 s2[256][17];
    const int bx = blockIdx.x, tid = threadIdx.x;
    if (bx < PB_APACK){
        apack_body(enc, bx >> 5, bx & 31, s2, tid);
    } else if (bx < PB_APACK + PB_WCPACK){
        wcpack_body(Wc, bx - PB_APACK, tid);
    } else if (bx < PB_APACK + PB_WCPACK + PB_WS){
        ws_body(h, Wb, bx - (PB_APACK + PB_WCPACK), tid);
    } else {
        zero_body(out, bx - (PB_APACK + PB_WCPACK + PB_WS), tid);
    }
}

// ---------------------------------------------------------------- score
// Fused fp16-MMA score GEMM + tanh/Wa epilogue. 256 threads, 8 warps (4x2),
// warp tile 64x64, BK=64. 2-stage pipeline, 2 CTAs/SM for latency hiding.
__global__ __launch_bounds__(256,2) void score_kernel(const float* __restrict__ Wa){
    extern __shared__ char sm[];
    const uint32_t sb = smem_u32(sm);
    float* smf = (float*)sm;
    const int tid  = threadIdx.x;
    const int lane = tid & 31, warp = tid >> 5;
    const int g = lane >> 2, t = lane & 3;
    const int warpM = warp >> 1, warpN = warp & 1;
    const int cb = blockIdx.x;
    const int rb = blockIdx.y;
    const size_t rowBase = (size_t)rb * BM;
    const int colBase = cb * BN;

    if (tid < BN) smf[(OFF_WA>>2) + tid] = Wa[colBase + tid];

    const char* abase = (const char*)g_apack + (size_t)rb*524288;  // 32 tiles x 16KB
    const char* bbase = (const char*)g_wcb   + (size_t)cb*262144;  // 32 tiles x 8KB

    // prologue: stages 0,1 (each 32KB A + 16KB B)
    #pragma unroll
    for (int s=0;s<2;s++){
        #pragma unroll
        for (int i=0;i<8;i++)
            cp16(sb + OFF_A + s*32768u + (uint32_t)(tid*16 + i*4096),
                 abase + (size_t)s*32768 + tid*16 + i*4096);
        #pragma unroll
        for (int i=0;i<4;i++)
            cp16(sb + OFF_B + s*16384u + (uint32_t)(tid*16 + i*4096),
                 bbase + (size_t)s*16384 + tid*16 + i*4096);
        asm volatile("cp.async.commit_group;" ::: "memory");
    }

    float acc[4][8][4];
    #pragma unroll
    for (int mf=0;mf<4;mf++)
        #pragma unroll
        for (int nf=0;nf<8;nf++)
            #pragma unroll
            for (int c=0;c<4;c++) acc[mf][nf][c] = 0.f;

    for (int kb=0; kb<NKI; kb++){
        asm volatile("cp.async.wait_group 1;" ::: "memory");
        __syncthreads();

        const uint32_t Ab = sb + OFF_A + (uint32_t)((kb&1)*32768);
        const uint32_t Bb = sb + OFF_B + (uint32_t)((kb&1)*16384);
        #pragma unroll
        for (int ks=0; ks<4; ks++){
            const uint32_t kseg = (uint32_t)(ks>>1), kk = (uint32_t)(ks&1);
            uint32_t a[4][4], bq[4][4];
            #pragma unroll
            for (int mf=0;mf<4;mf++)
                lds128(a[mf], Ab + kseg*16384u
                       + (uint32_t)((((warpM*4+mf)*2 + kk)*32 + lane)*16));
            #pragma unroll
            for (int p=0;p<4;p++)
                lds128(bq[p], Bb + kseg*8192u
                       + (uint32_t)((((warpN*4+p)*2 + kk)*32 + lane)*16));
            #pragma unroll
            for (int mf=0;mf<4;mf++)
                #pragma unroll
                for (int nf=0;nf<8;nf++)
                    mma_f16(acc[mf][nf], a[mf],
                            bq[nf>>1][(nf&1)*2], bq[nf>>1][(nf&1)*2+1]);
        }

        __syncthreads();
        if (kb+2 < NKI){
            const int s = kb & 1;   // slot just freed
            #pragma unroll
            for (int i=0;i<8;i++)
                cp16(sb + OFF_A + s*32768u + (uint32_t)(tid*16 + i*4096),
                     abase + (size_t)(kb+2)*32768 + tid*16 + i*4096);
            #pragma unroll
            for (int i=0;i<4;i++)
                cp16(sb + OFF_B + s*16384u + (uint32_t)(tid*16 + i*4096),
                     bbase + (size_t)(kb+2)*16384 + tid*16 + i*4096);
        }
        asm volatile("cp.async.commit_group;" ::: "memory");
    }

    // epilogue: tanh(H + ws) . Wa, row-reduce over t, atomic into g_score
    #pragma unroll
    for (int mf=0;mf<4;mf++){
        const int r0 = warpM*64 + mf*16 + g;
        const float* ws0 = g_ws + (size_t)( r0      & 31)*DDIM;
        const float* ws1 = g_ws + (size_t)((r0 + 8) & 31)*DDIM;
        float s0 = 0.f, s1 = 0.f;
        #pragma unroll
        for (int nf=0;nf<8;nf++){
            const int dl = warpN*64 + nf*8 + t*2;
            const int d0 = colBase + dl;
            const float wa0 = smf[(OFF_WA>>2) + dl];
            const float wa1 = smf[(OFF_WA>>2) + dl + 1];
            s0 += fast_tanh(acc[mf][nf][0] + ws0[d0  ]) * wa0
                + fast_tanh(acc[mf][nf][1] + ws0[d0+1]) * wa1;
            s1 += fast_tanh(acc[mf][nf][2] + ws1[d0  ]) * wa0
                + fast_tanh(acc[mf][nf][3] + ws1[d0+1]) * wa1;
        }
        s0 += __shfl_xor_sync(0xffffffffu, s0, 1);
        s0 += __shfl_xor_sync(0xffffffffu, s0, 2);
        s1 += __shfl_xor_sync(0xffffffffu, s1, 1);
        s1 += __shfl_xor_sync(0xffffffffu, s1, 2);
        if (t == 0){
            atomicAdd(&g_score[rowBase + r0    ], s0);
            atomicAdd(&g_score[rowBase + r0 + 8], s1);
        }
    }
}

// Single-pass softmax over s per batch b.
__global__ __launch_bounds__(256) void softmax_kernel(){
    __shared__ float red[8];
    int b = blockIdx.x, tid = threadIdx.x;
    float v[8]; float m = -3.4e38f;
    #pragma unroll
    for (int i=0;i<8;i++){ v[i] = g_score[(i*256+tid)*BATCH + b]; m = fmaxf(m, v[i]); }
    #pragma unroll
    for (int o=16;o>0;o>>=1) m = fmaxf(m, __shfl_xor_sync(0xffffffffu, m, o));
    if ((tid&31)==0) red[tid>>5] = m;
    __syncthreads();
    float mm = red[0];
    #pragma unroll
    for (int i=1;i<8;i++) mm = fmaxf(mm, red[i]);
    __syncthreads();
    float ssum = 0.f;
    #pragma unroll
    for (int i=0;i<8;i++){ v[i] = __expf(v[i]-mm); ssum += v[i]; }
    #pragma unroll
    for (int o=16;o>0;o>>=1) ssum += __shfl_xor_sync(0xffffffffu, ssum, o);
    if ((tid&31)==0) red[tid>>5] = ssum;
    __syncthreads();
    float tot = 0.f;
    #pragma unroll
    for (int i=0;i<8;i++) tot += red[i];
    float inv = 1.f/tot;
    #pragma unroll
    for (int i=0;i<8;i++) g_attn[(i*256+tid)*BATCH + b] = v[i]*inv;
}

// context[b,e] = sum_s attn[s,b] * enc[s,b,e], reading fp16 g_apack (uint4,
// fully coalesced). Block: one b-pair (b_lo, b_lo+8), 256 threads cover all
// 1024 k. Grid: (1, 16 b-pairs, 128 s-chunks of 16).
__global__ __launch_bounds__(256) void context_kernel(float* __restrict__ out){
    const int tid = threadIdx.x;
    const int bp  = blockIdx.y;                 // 0..15
    const int b_lo = (bp & 7) + ((bp >> 3) << 4);   // {0..7, 16..23}
    const int kb = tid >> 3;                    // 0..31
    const int ks = (tid >> 2) & 1;
    const int t  = tid & 3;
    const int kbase = kb*32 + ks*16 + 2*t;      // covers k, k+1, k+8, k+9
    const int s0 = blockIdx.z << 4;             // 16 s per chunk
    const int fpart = ks*32 + (bp & 7)*4 + t;   // f minus mgrp term
    const int mgadd = (bp >> 3);

    float a00=0.f, a01=0.f, a10=0.f, a11=0.f;   // b_lo: k,k+1,k+8,k+9
    float b00=0.f, b01=0.f, b10=0.f, b11=0.f;   // b_lo+8
    #pragma unroll 4
    for (int s=s0; s<s0+16; s++){
        const int R = s >> 3;
        const int mgrp = ((s & 7) << 1) + mgadd;
        const uint4 q = *(const uint4*)((const char*)g_apack
            + (size_t)(R*32 + kb)*16384 + (size_t)((mgrp*64) + fpart)*16);
        const float w0 = g_attn[s*BATCH + b_lo];
        const float w1 = g_attn[s*BATCH + b_lo + 8];
        float2 v0 = __half22float2(*(const __half2*)&q.x);
        float2 v1 = __half22float2(*(const __half2*)&q.y);
        float2 v2 = __half22float2(*(const __half2*)&q.z);
        float2 v3 = __half22float2(*(const __half2*)&q.w);
        a00 = fmaf(w0, v0.x, a00); a01 = fmaf(w0, v0.y, a01);
        b00 = fmaf(w1, v1.x, b00); b01 = fmaf(w1, v1.y, b01);
        a10 = fmaf(w0, v2.x, a10); a11 = fmaf(w0, v2.y, a11);
        b10 = fmaf(w1, v3.x, b10); b11 = fmaf(w1, v3.y, b11);
    }
    float* o0 = out + (size_t)b_lo*E2V + kbase;
    float* o1 = out + (size_t)(b_lo+8)*E2V + kbase;
    atomicAdd(o0+0, a00); atomicAdd(o0+1, a01);
    atomicAdd(o0+8, a10); atomicAdd(o0+9, a11);
    atomicAdd(o1+0, b00); atomicAdd(o1+1, b01);
    atomicAdd(o1+8, b10); atomicAdd(o1+9, b11);
}

extern "C" void kernel_launch(void* const* d_in, const int* in_sizes, int n_in,
                              void* d_out, int out_size){
    const float* h   = (const float*)d_in[0];   // [B, D]
    const float* enc = (const float*)d_in[1];   // [S, B, E2]
    const float* Wb  = (const float*)d_in[2];   // [D, D]
    const float* Wc  = (const float*)d_in[3];   // [D, E2]
    const float* Wa  = (const float*)d_in[4];   // [D]
    float* out = (float*)d_out;                 // [1, B, E2]

    cudaFuncSetAttribute(score_kernel,
                         cudaFuncAttributeMaxDynamicSharedMemorySize, SMEM_TOTAL);

    prepass_kernel<<<PB_TOTAL, 256>>>(enc, Wc, h, Wb, out);
    score_kernel  <<<dim3(NCB, NRB), 256, SMEM_TOTAL>>>(Wa);
    softmax_kernel<<<BATCH, 256>>>();
    context_kernel<<<dim3(1, 16, SLEN/16), 256>>>(out);
}